// round 14
// baseline (speedup 1.0000x reference)
#include <cuda_runtime.h>
#include <cuda_fp16.h>
#include <cstdint>

#define BB   4
#define NN   4096
#define DD   1024
#define AP   256
#define QS   0.06f

#define NSTAGE 3
#define ST_OF(T) ((T)==3 ? 32768u : (T)==2 ? 24576u : 16384u)
#define SM3    (NSTAGE*32768)
#define SM2    (NSTAGE*24576)
#define SM1    (NSTAGE*16384)

// ---------------------------------------------------------------------------
// device scratch (allocation-free rule)
// ---------------------------------------------------------------------------
__device__ __align__(16) __half g_xh[BB*NN*DD], g_xl[BB*NN*DD];
__device__ __align__(16) __half g_WkTh[DD*DD], g_WkTl[DD*DD];
__device__ __align__(16) __half g_WqTh[DD*DD], g_WqTl[DD*DD];
__device__ __align__(16) __half g_WvTh[DD*DD], g_WvTl[DD*DD];
__device__ __align__(16) __half g_Woh[DD*DD], g_Wol[DD*DD];
__device__ __align__(16) __half g_Gh[DD*DD];
__device__ __align__(16) __half g_W2h[DD*DD];
__device__ __align__(16) __half g_Zh[BB*NN*DD];
__device__ __align__(16) __half g_Uh[BB*NN*DD];
__device__ __align__(16) __half g_Ph[(size_t)BB*NN*NN];

// ---------------------------------------------------------------------------
// PTX helpers — baseline (non-arch-specific) instructions only
// ---------------------------------------------------------------------------
__device__ __forceinline__ uint32_t smem_u32(const void* p) {
    uint32_t a;
    asm("{ .reg .u64 t; cvta.to.shared.u64 t, %1; cvt.u32.u64 %0, t; }" : "=r"(a) : "l"(p));
    return a;
}
__device__ __forceinline__ void cp16(uint32_t s, const void* g) {
    asm volatile("cp.async.cg.shared.global [%0], [%1], 16;" :: "r"(s), "l"(g));
}
__device__ __forceinline__ void ldsm4(uint32_t* r, uint32_t a) {
    asm volatile("ldmatrix.sync.aligned.m8n8.x4.shared.b16 {%0,%1,%2,%3}, [%4];"
        : "=r"(r[0]), "=r"(r[1]), "=r"(r[2]), "=r"(r[3]) : "r"(a));
}
__device__ __forceinline__ void ldsm4t(uint32_t* r, uint32_t a) {
    asm volatile("ldmatrix.sync.aligned.m8n8.x4.trans.shared.b16 {%0,%1,%2,%3}, [%4];"
        : "=r"(r[0]), "=r"(r[1]), "=r"(r[2]), "=r"(r[3]) : "r"(a));
}
__device__ __forceinline__ void mmah(float* d, const uint32_t* a, const uint32_t* b) {
    asm volatile("mma.sync.aligned.m16n8k16.row.col.f32.f16.f16.f32 "
        "{%0,%1,%2,%3}, {%4,%5,%6,%7}, {%8,%9}, {%0,%1,%2,%3};"
        : "+f"(d[0]), "+f"(d[1]), "+f"(d[2]), "+f"(d[3])
        : "r"(a[0]), "r"(a[1]), "r"(a[2]), "r"(a[3]), "r"(b[0]), "r"(b[1]));
}
#define SW64(off)  ((off) ^ (((off) >> 3) & 0x30))
#define SW256(off) ((off) ^ (((off) >> 4) & 0x70))

// ===========================================================================
// dense NT GEMM pipeline (fp16 split; 64B smem rows, K-chunks of 32)
// TERMS==3: Ah·Bh + Al·Bh + Ah·Bl  | TERMS==2: Ah·Bh + Al·Bh | TERMS==1: Ah·Bh
// ===========================================================================
template<int TERMS>
__device__ __forceinline__ void issue_chunk(
    uint32_t sbase, int tid,
    const __half* pAh, const __half* pAl, const __half* pBh, const __half* pBl,
    int Kd, int k0)
{
    const uint32_t BOFF = (TERMS >= 2) ? 16384u : 8192u;
#pragma unroll
    for (int j = 0; j < 2; j++) {
        int e = tid + (j << 8);
        int r = e >> 2, c = e & 3;
        uint32_t sw = SW64((uint32_t)(r << 6) + (c << 4));
        size_t g = (size_t)r * Kd + k0 + (c << 3);
        cp16(sbase + sw, pAh + g);
        if (TERMS >= 2) cp16(sbase + 8192u + sw, pAl + g);
        cp16(sbase + BOFF + sw, pBh + g);
        if (TERMS == 3) cp16(sbase + 24576u + sw, pBl + g);
    }
    asm volatile("cp.async.commit_group;" ::: "memory");
}

template<int TERMS>
__device__ __forceinline__ void compute_chunk(
    float acc[4][4][4], uint32_t sb, int lane, int warp_m, int warp_n)
{
    const uint32_t BOFF = (TERMS >= 2) ? 16384u : 8192u;
#pragma unroll
    for (int ks = 0; ks < 2; ks++) {
        uint32_t ah[4][4], al[4][4], bh[4][2], bl[4][2];
#pragma unroll
        for (int mi = 0; mi < 4; mi++) {
            int row = warp_m*64 + mi*16 + ((lane >> 3) & 1)*8 + (lane & 7);
            int kb  = ks*32 + (lane >> 4)*16;
            uint32_t a = sb + SW64((uint32_t)(row << 6) + kb);
            ldsm4(ah[mi], a);
            if (TERMS >= 2) ldsm4(al[mi], a + 8192u);
        }
#pragma unroll
        for (int nj = 0; nj < 2; nj++) {
            int nr = warp_n*32 + nj*16 + (lane >> 4)*8 + (lane & 7);
            int kb = ks*32 + ((lane >> 3) & 1)*16;
            uint32_t a = sb + BOFF + SW64((uint32_t)(nr << 6) + kb);
            uint32_t t[4];
            ldsm4(t, a);
            bh[nj*2][0] = t[0]; bh[nj*2][1] = t[1];
            bh[nj*2+1][0] = t[2]; bh[nj*2+1][1] = t[3];
            if (TERMS == 3) {
                ldsm4(t, a + 8192u);
                bl[nj*2][0] = t[0]; bl[nj*2][1] = t[1];
                bl[nj*2+1][0] = t[2]; bl[nj*2+1][1] = t[3];
            }
        }
#pragma unroll
        for (int mi = 0; mi < 4; mi++)
#pragma unroll
            for (int ni = 0; ni < 4; ni++) {
                mmah(acc[mi][ni], ah[mi], bh[ni]);
                if (TERMS >= 2) mmah(acc[mi][ni], al[mi], bh[ni]);
                if (TERMS == 3) mmah(acc[mi][ni], ah[mi], bl[ni]);
            }
    }
}

template<int TERMS>
__device__ __forceinline__ void hmma_loop(
    float acc[4][4][4], char* smem, int tid,
    const __half* pAh, const __half* pAl,
    const __half* pBh, const __half* pBl, int Kd)
{
    const int lane = tid & 31, wid = tid >> 5;
    const int warp_m = wid >> 2, warp_n = wid & 3;
    const uint32_t STG = ST_OF(TERMS);
    uint32_t sb0 = smem_u32(smem);
    const int KC = Kd >> 5;

    issue_chunk<TERMS>(sb0,       tid, pAh, pAl, pBh, pBl, Kd, 0);
    issue_chunk<TERMS>(sb0 + STG, tid, pAh, pAl, pBh, pBl, Kd, 32);

    for (int i = 0; i < KC; i++) {
        if (i + 2 < KC) {
            issue_chunk<TERMS>(sb0 + ((i + 2) % NSTAGE)*STG, tid,
                               pAh, pAl, pBh, pBl, Kd, (i + 2) << 5);
            asm volatile("cp.async.wait_group 2;" ::: "memory");
        } else {
            asm volatile("cp.async.wait_group 0;" ::: "memory");
        }
        __syncthreads();
        compute_chunk<TERMS>(acc, sb0 + (i % NSTAGE)*STG, lane, warp_m, warp_n);
        __syncthreads();
    }
}

// epilogue: single-h fp16 store
__device__ __forceinline__ void store_h(
    float acc[4][4][4], __half* C, int row0, int col0, int lane, int warp_m, int warp_n)
{
    const int rb = row0 + warp_m*64 + (lane >> 2);
    const int cb = col0 + warp_n*32 + (lane & 3)*2;
#pragma unroll
    for (int mi = 0; mi < 4; mi++)
#pragma unroll
        for (int ni = 0; ni < 4; ni++)
#pragma unroll
            for (int h = 0; h < 2; h++) {
                size_t o = (size_t)(rb + mi*16 + 8*h) * DD + cb + ni*8;
                *(__half2*)&C[o] = __halves2half2(
                    __float2half(acc[mi][ni][2*h + 0]),
                    __float2half(acc[mi][ni][2*h + 1]));
            }
}

// ---------------------------------------------------------------------------
// merged weight GEMMs: z==0: G = WkT @ WqT^T ; z==1: W2 = Wo @ WvT^T (3-term)
// grid (8, 8, 2)
// ---------------------------------------------------------------------------
__global__ void __launch_bounds__(256, 1) wgemm_tc(
    const __half* __restrict__ A0h, const __half* __restrict__ A0l,
    const __half* __restrict__ B0h, const __half* __restrict__ B0l,
    __half* __restrict__ C0,
    const __half* __restrict__ A1h, const __half* __restrict__ A1l,
    const __half* __restrict__ B1h, const __half* __restrict__ B1l,
    __half* __restrict__ C1)
{
    extern __shared__ char smem[];
    const int tid = threadIdx.x, lane = tid & 31, wid = tid >> 5;
    const int warp_m = wid >> 2, warp_n = wid & 3;
    const int row0 = blockIdx.y << 7, col0 = blockIdx.x << 7;
    const bool z1 = (blockIdx.z != 0);
    const __half* Ah = (z1 ? A1h : A0h) + (size_t)row0 * DD;
    const __half* Al = (z1 ? A1l : A0l) + (size_t)row0 * DD;
    const __half* Bh = (z1 ? B1h : B0h) + (size_t)col0 * DD;
    const __half* Bl = (z1 ? B1l : B0l) + (size_t)col0 * DD;
    __half* C = z1 ? C1 : C0;

    float acc[4][4][4] = {};
    hmma_loop<3>(acc, smem, tid, Ah, Al, Bh, Bl, DD);
    store_h(acc, C, row0, col0, lane, warp_m, warp_n);
}

// ---------------------------------------------------------------------------
// merged activation GEMMs: z==0: Z = x @ G^T (2-term) ; z==1: U = xh @ W2^T (1-term)
// grid (8, 128, 2)
// ---------------------------------------------------------------------------
__global__ void __launch_bounds__(256, 1) zu_tc(
    const __half* __restrict__ xh, const __half* __restrict__ xl,
    const __half* __restrict__ Gh, const __half* __restrict__ W2h,
    __half* __restrict__ Zh, __half* __restrict__ Uh)
{
    extern __shared__ char smem[];
    const int tid = threadIdx.x, lane = tid & 31, wid = tid >> 5;
    const int warp_m = wid >> 2, warp_n = wid & 3;
    const int row0 = blockIdx.y << 7, col0 = blockIdx.x << 7;

    float acc[4][4][4] = {};
    if (blockIdx.z == 0) {
        hmma_loop<2>(acc, smem, tid,
                     xh + (size_t)row0 * DD, xl + (size_t)row0 * DD,
                     Gh + (size_t)col0 * DD, nullptr, DD);
        store_h(acc, Zh, row0, col0, lane, warp_m, warp_n);
    } else {
        hmma_loop<1>(acc, smem, tid,
                     xh + (size_t)row0 * DD, nullptr,
                     W2h + (size_t)col0 * DD, nullptr, DD);
        store_h(acc, Uh, row0, col0, lane, warp_m, warp_n);
    }
}

// ---------------------------------------------------------------------------
// banded logits: att[b,n,m] = QS * Zh[b,n]·xh[b,m], |n-m| < AP  (1-term)
// distributed zeroing of out-of-window columns across the 5 blocks per strip
// ---------------------------------------------------------------------------
__global__ void __launch_bounds__(256, 1) band_tc(
    const __half* __restrict__ Zh, const __half* __restrict__ xh,
    float* __restrict__ att)
{
    const int it = blockIdx.y;
    const int jt = it + (int)blockIdx.x - 2;
    const int bz = blockIdx.z;
    const int tid = threadIdx.x;
    float* attb = att + ((size_t)bz << 24);
    const int row0 = it << 7;
    const int lane = tid & 31, wid = tid >> 5;

    {
        int lo_t = it - 2; if (lo_t < 0) lo_t = 0;
        int hi_t = it + 2; if (hi_t > 31) hi_t = 31;
        const int cL4 = lo_t << 5;
        const int cR0 = (hi_t + 1) << 5;
        float4 z4 = make_float4(0.f, 0.f, 0.f, 0.f);
        for (int j = wid; ; j += 8) {
            int r = (int)blockIdx.x + 5 * j;
            if (r >= 128) break;
            float4* rp = (float4*)(attb + (size_t)(row0 + r) * NN);
            for (int c = lane; c < cL4; c += 32) rp[c] = z4;
            for (int c = cR0 + lane; c < (NN >> 2); c += 32) rp[c] = z4;
        }
    }
    if (jt < 0 || jt >= (NN >> 7)) return;

    extern __shared__ char smem[];
    const int warp_m = wid >> 2, warp_n = wid & 3;
    const int col0 = jt << 7;
    const size_t boff = (size_t)bz << 22;

    float acc[4][4][4] = {};
    hmma_loop<1>(acc, smem, tid,
                 Zh + boff + (size_t)row0 * DD, nullptr,
                 xh + boff + (size_t)col0 * DD, nullptr, DD);

    const int rb = row0 + warp_m*64 + (lane >> 2);
    const int cb = col0 + warp_n*32 + (lane & 3)*2;
#pragma unroll
    for (int mi = 0; mi < 4; mi++)
#pragma unroll
        for (int ni = 0; ni < 4; ni++)
#pragma unroll
            for (int h = 0; h < 2; h++) {
                int gi = rb + mi*16 + 8*h;
                int gj = cb + ni*8;
                int d0 = gi - gj, d1 = gi - gj - 1;
                float w0 = (d0 > -AP && d0 < AP) ? acc[mi][ni][2*h + 0] * QS : 0.f;
                float w1 = (d1 > -AP && d1 < AP) ? acc[mi][ni][2*h + 1] * QS : 0.f;
                *(float2*)&attb[(size_t)gi * NN + gj] = make_float2(w0, w1);
            }
}

// ---------------------------------------------------------------------------
// splits & batched transpose
// ---------------------------------------------------------------------------
__global__ void split2(const float* __restrict__ in,
                       __half* __restrict__ h, __half* __restrict__ l, int n2)
{
    int i = blockIdx.x * blockDim.x + threadIdx.x;
    int st = gridDim.x * blockDim.x;
    for (; i < n2; i += st) {
        float2 v = ((const float2*)in)[i];
        __half hx = __float2half(v.x), hy = __float2half(v.y);
        ((__half2*)h)[i] = __halves2half2(hx, hy);
        ((__half2*)l)[i] = __halves2half2(__float2half(v.x - __half2float(hx)),
                                          __float2half(v.y - __half2float(hy)));
    }
}
__global__ void transpose_split3(
    const float* __restrict__ w0, __half* __restrict__ t0h, __half* __restrict__ t0l,
    const float* __restrict__ w1, __half* __restrict__ t1h, __half* __restrict__ t1l,
    const float* __restrict__ w2, __half* __restrict__ t2h, __half* __restrict__ t2l)
{
    const float* in = (blockIdx.z == 0) ? w0 : (blockIdx.z == 1) ? w1 : w2;
    __half* th = (blockIdx.z == 0) ? t0h : (blockIdx.z == 1) ? t1h : t2h;
    __half* tl = (blockIdx.z == 0) ? t0l : (blockIdx.z == 1) ? t1l : t2l;
    __shared__ float t[32][33];
    int bx = blockIdx.x << 5, by = blockIdx.y << 5;
#pragma unroll
    for (int k = 0; k < 32; k += 8)
        t[threadIdx.y + k][threadIdx.x] = in[(size_t)(by + threadIdx.y + k) * DD + bx + threadIdx.x];
    __syncthreads();
#pragma unroll
    for (int k = 0; k < 32; k += 8) {
        int r = bx + threadIdx.y + k, c = by + threadIdx.x;
        float v = t[threadIdx.x][threadIdx.y + k];
        __half h = __float2half(v);
        th[(size_t)r * DD + c] = h;
        tl[(size_t)r * DD + c] = __float2half(v - __half2float(h));
    }
}

// ---------------------------------------------------------------------------
// band softmax + fp16 P emit over padded window
// ---------------------------------------------------------------------------
__global__ void __launch_bounds__(128) band_softmax(
    float* __restrict__ att, __half* __restrict__ Ph)
{
    __shared__ float red[4];
    const int gid = blockIdx.x;
    const int b = gid >> 12;
    const int i = gid & (NN - 1);
    const size_t rowbase = ((size_t)b << 24) + ((size_t)i << 12);
    float* row = att + rowbase;
    int jlo = i - (AP - 1); if (jlo < 0) jlo = 0;
    int jhi = i + (AP - 1); if (jhi > NN - 1) jhi = NN - 1;
    const int cnt = jhi - jlo + 1;

    float v[4];
    int nc = 0;
    float m = -1e30f;
    for (int t = threadIdx.x; t < cnt; t += 128) { v[nc] = row[jlo + t]; m = fmaxf(m, v[nc]); nc++; }
    for (int o = 16; o > 0; o >>= 1) m = fmaxf(m, __shfl_xor_sync(0xffffffffu, m, o));
    const int w = threadIdx.x >> 5;
    if ((threadIdx.x & 31) == 0) red[w] = m;
    __syncthreads();
    m = fmaxf(fmaxf(red[0], red[1]), fmaxf(red[2], red[3]));
    __syncthreads();

    float s = 0.f;
    for (int c = 0; c < nc; c++) { v[c] = __expf(v[c] - m); s += v[c]; }
    for (int o = 16; o > 0; o >>= 1) s += __shfl_xor_sync(0xffffffffu, s, o);
    if ((threadIdx.x & 31) == 0) red[w] = s;
    __syncthreads();
    s = red[0] + red[1] + red[2] + red[3];
    const float inv = 1.0f / s;

    nc = 0;
    for (int t = threadIdx.x; t < cnt; t += 128) { row[jlo + t] = v[nc] * inv; nc++; }
    __syncthreads();

    int wlo = i - 256; wlo &= ~127; if (wlo < 0) wlo = 0;
    int whi = (i + 384) & ~127; if (whi > NN) whi = NN;
    for (int n = wlo + threadIdx.x; n < whi; n += 128) {
        float f = (n >= jlo && n <= jhi) ? row[n] : 0.f;
        Ph[rowbase + n] = __float2half(f);
    }
}

// ===========================================================================
// ptv: y[b,n,i] = sum_m P[b,m,n] * U[b,m,i]   (banded, 1-term, trans-ldsm)
// ===========================================================================
__device__ __forceinline__ void ptv_issue(
    uint32_t sbase, int tid,
    const __half* Phg, const __half* Uhg, int m0, int n0, int o0)
{
#pragma unroll
    for (int j = 0; j < 2; j++) {
        int e = tid + (j << 8);
        int r = e >> 4, c16 = e & 15;
        uint32_t sw = SW256((uint32_t)(r << 8) + (c16 << 4));
        cp16(sbase +         sw, Phg + (size_t)(m0 + r) * NN + n0 + (c16 << 3));
        cp16(sbase + 8192u + sw, Uhg + (size_t)(m0 + r) * DD + o0 + (c16 << 3));
    }
    asm volatile("cp.async.commit_group;" ::: "memory");
}

__device__ __forceinline__ void ptv_compute(
    float acc[4][4][4], uint32_t sb, int lane, int warp_m, int warp_n)
{
#pragma unroll
    for (int ks = 0; ks < 2; ks++) {
        const int m16 = ks << 4;
        uint32_t ah[4][4], bh[4][2];
        const int ar = m16 + ((lane >> 4) << 3) + (lane & 7);
        const int acsel = ((lane >> 3) & 1) << 3;
#pragma unroll
        for (int mi = 0; mi < 4; mi++) {
            int nb = warp_m*64 + mi*16 + acsel;
            ldsm4t(ah[mi], sb + SW256((uint32_t)(ar << 8) + (nb << 1)));
        }
        const int br = m16 + (((lane >> 3) & 1) << 3) + (lane & 7);
        const int bcsel = (lane >> 4) << 3;
#pragma unroll
        for (int jb = 0; jb < 2; jb++) {
            int ob = warp_n*32 + jb*16 + bcsel;
            uint32_t t4[4];
            ldsm4t(t4, sb + 8192u + SW256((uint32_t)(br << 8) + (ob << 1)));
            bh[jb*2][0] = t4[0]; bh[jb*2][1] = t4[1];
            bh[jb*2+1][0] = t4[2]; bh[jb*2+1][1] = t4[3];
        }
#pragma unroll
        for (int mi = 0; mi < 4; mi++)
#pragma unroll
            for (int ni = 0; ni < 4; ni++)
                mmah(acc[mi][ni], ah[mi], bh[ni]);
    }
}

__global__ void __launch_bounds__(256, 1) ptv_tc(
    const __half* __restrict__ Phg, const __half* __restrict__ Uhg,
    float* __restrict__ yout)
{
    const int bz = blockIdx.z;
    const int n0 = blockIdx.y << 7;
    const int o0 = blockIdx.x << 7;
    const __half* Pb = Phg + ((size_t)bz << 24);
    const __half* Ub = Uhg + ((size_t)bz << 22);

    extern __shared__ char smem[];
    uint32_t sb0 = smem_u32(smem);
    const int tid = threadIdx.x, lane = tid & 31, wid = tid >> 5;
    const int warp_m = wid >> 2, warp_n = wid & 3;

    int mlo = n0 - 256; if (mlo < 0) mlo = 0;
    int mhe = n0 + 384; if (mhe > NN) mhe = NN;
    const int NC = (mhe - mlo) >> 5;

    float acc[4][4][4] = {};

    ptv_issue(sb0,          tid, Pb, Ub, mlo,      n0, o0);
    ptv_issue(sb0 + 16384u, tid, Pb, Ub, mlo + 32, n0, o0);

    for (int i = 0; i < NC; i++) {
        if (i + 2 < NC) {
            ptv_issue(sb0 + ((i + 2) % NSTAGE)*16384u, tid,
                      Pb, Ub, mlo + ((i + 2) << 5), n0, o0);
            asm volatile("cp.async.wait_group 2;" ::: "memory");
        } else {
            asm volatile("cp.async.wait_group 0;" ::: "memory");
        }
        __syncthreads();
        ptv_compute(acc, sb0 + (i % NSTAGE)*16384u, lane, warp_m, warp_n);
        __syncthreads();
    }

    float* yb = yout + ((size_t)bz << 22);
    const int rb = n0 + warp_m*64 + (lane >> 2);
    const int cb = o0 + warp_n*32 + (lane & 3)*2;
#pragma unroll
    for (int mi = 0; mi < 4; mi++)
#pragma unroll
        for (int ni = 0; ni < 4; ni++)
#pragma unroll
            for (int h = 0; h < 2; h++) {
                size_t off = (size_t)(rb + mi*16 + 8*h) * DD + cb + ni*8;
                *(float2*)&yb[off] = make_float2(acc[mi][ni][2*h + 0],
                                                 acc[mi][ni][2*h + 1]);
            }
}

// ---------------------------------------------------------------------------
extern "C" void kernel_launch(void* const* d_in, const int* in_sizes, int n_in,
                              void* d_out, int out_size)
{
    const float* x  = (const float*)d_in[0];
    const float* Wk = (const float*)d_in[1];
    const float* Wq = (const float*)d_in[2];
    const float* Wv = (const float*)d_in[3];
    const float* Wo = (const float*)d_in[4];

    float* y_out   = (float*)d_out;
    float* att_out = y_out + (size_t)BB * NN * DD;

    __half *xh, *xl, *WkTh, *WkTl, *WqTh, *WqTl, *WvTh, *WvTl, *Woh, *Wol;
    __half *Gh, *W2h, *Zh, *Uh, *Ph;
    cudaGetSymbolAddress((void**)&xh,   g_xh);   cudaGetSymbolAddress((void**)&xl,   g_xl);
    cudaGetSymbolAddress((void**)&WkTh, g_WkTh); cudaGetSymbolAddress((void**)&WkTl, g_WkTl);
    cudaGetSymbolAddress((void**)&WqTh, g_WqTh); cudaGetSymbolAddress((void**)&WqTl, g_WqTl);
    cudaGetSymbolAddress((void**)&WvTh, g_WvTh); cudaGetSymbolAddress((void**)&WvTl, g_WvTl);
    cudaGetSymbolAddress((void**)&Woh,  g_Woh);  cudaGetSymbolAddress((void**)&Wol,  g_Wol);
    cudaGetSymbolAddress((void**)&Gh,   g_Gh);   cudaGetSymbolAddress((void**)&W2h,  g_W2h);
    cudaGetSymbolAddress((void**)&Zh,   g_Zh);
    cudaGetSymbolAddress((void**)&Uh,   g_Uh);   cudaGetSymbolAddress((void**)&Ph,   g_Ph);

    cudaFuncSetAttribute((const void*)wgemm_tc, cudaFuncAttributeMaxDynamicSharedMemorySize, SM3);
    cudaFuncSetAttribute((const void*)zu_tc,    cudaFuncAttributeMaxDynamicSharedMemorySize, SM2);
    cudaFuncSetAttribute((const void*)band_tc,  cudaFuncAttributeMaxDynamicSharedMemorySize, SM1);
    cudaFuncSetAttribute((const void*)ptv_tc,   cudaFuncAttributeMaxDynamicSharedMemorySize, SM1);

    // 1. operand prep
    split2<<<4096, 256>>>(x, xh, xl, (BB * NN * DD) / 2);
    transpose_split3<<<dim3(32, 32, 3), dim3(32, 8)>>>(
        Wk, WkTh, WkTl, Wq, WqTh, WqTl, Wv, WvTh, WvTl);
    split2<<<512, 256>>>(Wo, Woh, Wol, (DD * DD) / 2);

    // 2. G = WkT @ WqT^T  and  W2 = Wo @ WvT^T  (one launch, 128 CTAs)
    wgemm_tc<<<dim3(8, 8, 2), 256, SM3>>>(WkTh, WkTl, WqTh, WqTl, Gh,
                                          Woh, Wol, WvTh, WvTl, W2h);

    // 3+4. Z = x @ G^T (2-term)  and  U = xh @ W2^T (1-term)  (one launch)
    zu_tc<<<dim3(8, 128, 2), 256, SM2>>>(xh, xl, Gh, W2h, Zh, Uh);

    // 5. banded logits = QS * Zh·xh^T (1-term; zeroes out-of-band att)
    band_tc<<<dim3(5, NN / 128, BB), 256, SM1>>>(Zh, xh, att_out);

    // 6. softmax + P emit
    band_softmax<<<BB * NN, 128>>>(att_out, Ph);

    // 7. y = P^T @ U (banded, 1-term, fp32 out — final)
    ptv_tc<<<dim3(DD / 128, NN / 128, BB), 256, SM1>>>(Ph, Uh, y_out);
}

// round 17
// speedup vs baseline: 1.1566x; 1.1566x over previous
#include <cuda_runtime.h>
#include <cuda_fp16.h>
#include <cstdint>

#define BB   4
#define NN   4096
#define DD   1024
#define AP   256
#define QS   0.06f

#define NSTAGE 4
#define ST_OF(T) ((T)==3 ? 32768u : (T)==2 ? 24576u : 16384u)
#define SM3    (NSTAGE*32768)
#define SM2    (NSTAGE*24576)
#define SM1    (NSTAGE*16384)

// ---------------------------------------------------------------------------
// device scratch (allocation-free rule)
// ---------------------------------------------------------------------------
__device__ __align__(16) __half g_xh[BB*NN*DD], g_xl[BB*NN*DD];
__device__ __align__(16) __half g_WkTh[DD*DD], g_WkTl[DD*DD];
__device__ __align__(16) __half g_WqTh[DD*DD], g_WqTl[DD*DD];
__device__ __align__(16) __half g_WvTh[DD*DD], g_WvTl[DD*DD];
__device__ __align__(16) __half g_Woh[DD*DD], g_Wol[DD*DD];
__device__ __align__(16) __half g_Gh[DD*DD];
__device__ __align__(16) __half g_W2h[DD*DD];
__device__ __align__(16) __half g_Zh[BB*NN*DD];
__device__ __align__(16) __half g_Uh[BB*NN*DD];
__device__ __align__(16) __half g_Ph[(size_t)BB*NN*NN];

// ---------------------------------------------------------------------------
// PTX helpers — baseline (non-arch-specific) instructions only
// ---------------------------------------------------------------------------
__device__ __forceinline__ uint32_t smem_u32(const void* p) {
    uint32_t a;
    asm("{ .reg .u64 t; cvta.to.shared.u64 t, %1; cvt.u32.u64 %0, t; }" : "=r"(a) : "l"(p));
    return a;
}
__device__ __forceinline__ void cp16(uint32_t s, const void* g) {
    asm volatile("cp.async.cg.shared.global [%0], [%1], 16;" :: "r"(s), "l"(g));
}
__device__ __forceinline__ void ldsm4(uint32_t* r, uint32_t a) {
    asm volatile("ldmatrix.sync.aligned.m8n8.x4.shared.b16 {%0,%1,%2,%3}, [%4];"
        : "=r"(r[0]), "=r"(r[1]), "=r"(r[2]), "=r"(r[3]) : "r"(a));
}
__device__ __forceinline__ void ldsm4t(uint32_t* r, uint32_t a) {
    asm volatile("ldmatrix.sync.aligned.m8n8.x4.trans.shared.b16 {%0,%1,%2,%3}, [%4];"
        : "=r"(r[0]), "=r"(r[1]), "=r"(r[2]), "=r"(r[3]) : "r"(a));
}
__device__ __forceinline__ void mmah(float* d, const uint32_t* a, const uint32_t* b) {
    asm volatile("mma.sync.aligned.m16n8k16.row.col.f32.f16.f16.f32 "
        "{%0,%1,%2,%3}, {%4,%5,%6,%7}, {%8,%9}, {%0,%1,%2,%3};"
        : "+f"(d[0]), "+f"(d[1]), "+f"(d[2]), "+f"(d[3])
        : "r"(a[0]), "r"(a[1]), "r"(a[2]), "r"(a[3]), "r"(b[0]), "r"(b[1]));
}
#define SW64(off)  ((off) ^ (((off) >> 3) & 0x30))
#define SW256(off) ((off) ^ (((off) >> 4) & 0x70))

// ===========================================================================
// dense NT GEMM pipeline (fp16 split; 64B smem rows, K-chunks of 32)
// 4 stages, prefetch depth 2, ONE barrier per chunk (race-free: a warp
// issuing into stage (i+2)%4 can only overlap a laggard in compute(i-1) on
// stage (i-1)%4; older laggards are excluded by the previous barrier)
// ===========================================================================
template<int TERMS>
__device__ __forceinline__ void issue_chunk(
    uint32_t sbase, int tid,
    const __half* pAh, const __half* pAl, const __half* pBh, const __half* pBl,
    int Kd, int k0)
{
    const uint32_t BOFF = (TERMS >= 2) ? 16384u : 8192u;
#pragma unroll
    for (int j = 0; j < 2; j++) {
        int e = tid + (j << 8);
        int r = e >> 2, c = e & 3;
        uint32_t sw = SW64((uint32_t)(r << 6) + (c << 4));
        size_t g = (size_t)r * Kd + k0 + (c << 3);
        cp16(sbase + sw, pAh + g);
        if (TERMS >= 2) cp16(sbase + 8192u + sw, pAl + g);
        cp16(sbase + BOFF + sw, pBh + g);
        if (TERMS == 3) cp16(sbase + 24576u + sw, pBl + g);
    }
    asm volatile("cp.async.commit_group;" ::: "memory");
}

template<int TERMS>
__device__ __forceinline__ void compute_chunk(
    float acc[4][4][4], uint32_t sb, int lane, int warp_m, int warp_n)
{
    const uint32_t BOFF = (TERMS >= 2) ? 16384u : 8192u;
#pragma unroll
    for (int ks = 0; ks < 2; ks++) {
        uint32_t ah[4][4], al[4][4], bh[4][2], bl[4][2];
#pragma unroll
        for (int mi = 0; mi < 4; mi++) {
            int row = warp_m*64 + mi*16 + ((lane >> 3) & 1)*8 + (lane & 7);
            int kb  = ks*32 + (lane >> 4)*16;
            uint32_t a = sb + SW64((uint32_t)(row << 6) + kb);
            ldsm4(ah[mi], a);
            if (TERMS >= 2) ldsm4(al[mi], a + 8192u);
        }
#pragma unroll
        for (int nj = 0; nj < 2; nj++) {
            int nr = warp_n*32 + nj*16 + (lane >> 4)*8 + (lane & 7);
            int kb = ks*32 + ((lane >> 3) & 1)*16;
            uint32_t a = sb + BOFF + SW64((uint32_t)(nr << 6) + kb);
            uint32_t t[4];
            ldsm4(t, a);
            bh[nj*2][0] = t[0]; bh[nj*2][1] = t[1];
            bh[nj*2+1][0] = t[2]; bh[nj*2+1][1] = t[3];
            if (TERMS == 3) {
                ldsm4(t, a + 8192u);
                bl[nj*2][0] = t[0]; bl[nj*2][1] = t[1];
                bl[nj*2+1][0] = t[2]; bl[nj*2+1][1] = t[3];
            }
        }
#pragma unroll
        for (int mi = 0; mi < 4; mi++)
#pragma unroll
            for (int ni = 0; ni < 4; ni++) {
                mmah(acc[mi][ni], ah[mi], bh[ni]);
                if (TERMS >= 2) mmah(acc[mi][ni], al[mi], bh[ni]);
                if (TERMS == 3) mmah(acc[mi][ni], ah[mi], bl[ni]);
            }
    }
}

template<int TERMS>
__device__ __forceinline__ void hmma_loop(
    float acc[4][4][4], char* smem, int tid,
    const __half* pAh, const __half* pAl,
    const __half* pBh, const __half* pBl, int Kd)
{
    const int lane = tid & 31, wid = tid >> 5;
    const int warp_m = wid >> 2, warp_n = wid & 3;
    const uint32_t STG = ST_OF(TERMS);
    uint32_t sb0 = smem_u32(smem);
    const int KC = Kd >> 5;

    issue_chunk<TERMS>(sb0,       tid, pAh, pAl, pBh, pBl, Kd, 0);
    issue_chunk<TERMS>(sb0 + STG, tid, pAh, pAl, pBh, pBl, Kd, 32);

    for (int i = 0; i < KC; i++) {
        if (i + 2 < KC) {
            issue_chunk<TERMS>(sb0 + ((i + 2) & 3)*STG, tid,
                               pAh, pAl, pBh, pBl, Kd, (i + 2) << 5);
            asm volatile("cp.async.wait_group 2;" ::: "memory");
        } else {
            asm volatile("cp.async.wait_group 0;" ::: "memory");
        }
        __syncthreads();
        compute_chunk<TERMS>(acc, sb0 + (i & 3)*STG, lane, warp_m, warp_n);
    }
}

// epilogue: single-h fp16 store
__device__ __forceinline__ void store_h(
    float acc[4][4][4], __half* C, int row0, int col0, int lane, int warp_m, int warp_n)
{
    const int rb = row0 + warp_m*64 + (lane >> 2);
    const int cb = col0 + warp_n*32 + (lane & 3)*2;
#pragma unroll
    for (int mi = 0; mi < 4; mi++)
#pragma unroll
        for (int ni = 0; ni < 4; ni++)
#pragma unroll
            for (int h = 0; h < 2; h++) {
                size_t o = (size_t)(rb + mi*16 + 8*h) * DD + cb + ni*8;
                *(__half2*)&C[o] = __halves2half2(
                    __float2half(acc[mi][ni][2*h + 0]),
                    __float2half(acc[mi][ni][2*h + 1]));
            }
}

// ---------------------------------------------------------------------------
// merged weight GEMMs: z==0: G = WkT @ WqT^T ; z==1: W2 = Wo @ WvT^T (3-term)
// ---------------------------------------------------------------------------
__global__ void __launch_bounds__(256, 1) wgemm_tc(
    const __half* __restrict__ A0h, const __half* __restrict__ A0l,
    const __half* __restrict__ B0h, const __half* __restrict__ B0l,
    __half* __restrict__ C0,
    const __half* __restrict__ A1h, const __half* __restrict__ A1l,
    const __half* __restrict__ B1h, const __half* __restrict__ B1l,
    __half* __restrict__ C1)
{
    extern __shared__ char smem[];
    const int tid = threadIdx.x, lane = tid & 31, wid = tid >> 5;
    const int warp_m = wid >> 2, warp_n = wid & 3;
    const int row0 = blockIdx.y << 7, col0 = blockIdx.x << 7;
    const bool z1 = (blockIdx.z != 0);
    const __half* Ah = (z1 ? A1h : A0h) + (size_t)row0 * DD;
    const __half* Al = (z1 ? A1l : A0l) + (size_t)row0 * DD;
    const __half* Bh = (z1 ? B1h : B0h) + (size_t)col0 * DD;
    const __half* Bl = (z1 ? B1l : B0l) + (size_t)col0 * DD;
    __half* C = z1 ? C1 : C0;

    float acc[4][4][4] = {};
    hmma_loop<3>(acc, smem, tid, Ah, Al, Bh, Bl, DD);
    store_h(acc, C, row0, col0, lane, warp_m, warp_n);
}

// ---------------------------------------------------------------------------
// merged activation GEMMs: z==0: Z = x @ G^T (2-term) ; z==1: U = xh @ W2^T (1-term)
// ---------------------------------------------------------------------------
__global__ void __launch_bounds__(256, 1) zu_tc(
    const __half* __restrict__ xh, const __half* __restrict__ xl,
    const __half* __restrict__ Gh, const __half* __restrict__ W2h,
    __half* __restrict__ Zh, __half* __restrict__ Uh)
{
    extern __shared__ char smem[];
    const int tid = threadIdx.x, lane = tid & 31, wid = tid >> 5;
    const int warp_m = wid >> 2, warp_n = wid & 3;
    const int row0 = blockIdx.y << 7, col0 = blockIdx.x << 7;

    float acc[4][4][4] = {};
    if (blockIdx.z == 0) {
        hmma_loop<2>(acc, smem, tid,
                     xh + (size_t)row0 * DD, xl + (size_t)row0 * DD,
                     Gh + (size_t)col0 * DD, nullptr, DD);
        store_h(acc, Zh, row0, col0, lane, warp_m, warp_n);
    } else {
        hmma_loop<1>(acc, smem, tid,
                     xh + (size_t)row0 * DD, nullptr,
                     W2h + (size_t)col0 * DD, nullptr, DD);
        store_h(acc, Uh, row0, col0, lane, warp_m, warp_n);
    }
}

// ---------------------------------------------------------------------------
// banded logits: att[b,n,m] = QS * Zh[b,n]·xh[b,m], |n-m| < AP  (1-term)
// distributed zeroing of out-of-window columns across the 5 blocks per strip
// ---------------------------------------------------------------------------
__global__ void __launch_bounds__(256, 1) band_tc(
    const __half* __restrict__ Zh, const __half* __restrict__ xh,
    float* __restrict__ att)
{
    const int it = blockIdx.y;
    const int jt = it + (int)blockIdx.x - 2;
    const int bz = blockIdx.z;
    const int tid = threadIdx.x;
    float* attb = att + ((size_t)bz << 24);
    const int row0 = it << 7;
    const int lane = tid & 31, wid = tid >> 5;

    {
        int lo_t = it - 2; if (lo_t < 0) lo_t = 0;
        int hi_t = it + 2; if (hi_t > 31) hi_t = 31;
        const int cL4 = lo_t << 5;
        const int cR0 = (hi_t + 1) << 5;
        float4 z4 = make_float4(0.f, 0.f, 0.f, 0.f);
        for (int j = wid; ; j += 8) {
            int r = (int)blockIdx.x + 5 * j;
            if (r >= 128) break;
            float4* rp = (float4*)(attb + (size_t)(row0 + r) * NN);
            for (int c = lane; c < cL4; c += 32) rp[c] = z4;
            for (int c = cR0 + lane; c < (NN >> 2); c += 32) rp[c] = z4;
        }
    }
    if (jt < 0 || jt >= (NN >> 7)) return;

    extern __shared__ char smem[];
    const int warp_m = wid >> 2, warp_n = wid & 3;
    const int col0 = jt << 7;
    const size_t boff = (size_t)bz << 22;

    float acc[4][4][4] = {};
    hmma_loop<1>(acc, smem, tid,
                 Zh + boff + (size_t)row0 * DD, nullptr,
                 xh + boff + (size_t)col0 * DD, nullptr, DD);

    const int rb = row0 + warp_m*64 + (lane >> 2);
    const int cb = col0 + warp_n*32 + (lane & 3)*2;
#pragma unroll
    for (int mi = 0; mi < 4; mi++)
#pragma unroll
        for (int ni = 0; ni < 4; ni++)
#pragma unroll
            for (int h = 0; h < 2; h++) {
                int gi = rb + mi*16 + 8*h;
                int gj = cb + ni*8;
                int d0 = gi - gj, d1 = gi - gj - 1;
                float w0 = (d0 > -AP && d0 < AP) ? acc[mi][ni][2*h + 0] * QS : 0.f;
                float w1 = (d1 > -AP && d1 < AP) ? acc[mi][ni][2*h + 1] * QS : 0.f;
                *(float2*)&attb[(size_t)gi * NN + gj] = make_float2(w0, w1);
            }
}

// ---------------------------------------------------------------------------
// splits & batched transpose
// ---------------------------------------------------------------------------
__global__ void split2(const float* __restrict__ in,
                       __half* __restrict__ h, __half* __restrict__ l, int n2)
{
    int i = blockIdx.x * blockDim.x + threadIdx.x;
    int st = gridDim.x * blockDim.x;
    for (; i < n2; i += st) {
        float2 v = ((const float2*)in)[i];
        __half hx = __float2half(v.x), hy = __float2half(v.y);
        ((__half2*)h)[i] = __halves2half2(hx, hy);
        ((__half2*)l)[i] = __halves2half2(__float2half(v.x - __half2float(hx)),
                                          __float2half(v.y - __half2float(hy)));
    }
}
__global__ void transpose_split3(
    const float* __restrict__ w0, __half* __restrict__ t0h, __half* __restrict__ t0l,
    const float* __restrict__ w1, __half* __restrict__ t1h, __half* __restrict__ t1l,
    const float* __restrict__ w2, __half* __restrict__ t2h, __half* __restrict__ t2l)
{
    const float* in = (blockIdx.z == 0) ? w0 : (blockIdx.z == 1) ? w1 : w2;
    __half* th = (blockIdx.z == 0) ? t0h : (blockIdx.z == 1) ? t1h : t2h;
    __half* tl = (blockIdx.z == 0) ? t0l : (blockIdx.z == 1) ? t1l : t2l;
    __shared__ float t[32][33];
    int bx = blockIdx.x << 5, by = blockIdx.y << 5;
#pragma unroll
    for (int k = 0; k < 32; k += 8)
        t[threadIdx.y + k][threadIdx.x] = in[(size_t)(by + threadIdx.y + k) * DD + bx + threadIdx.x];
    __syncthreads();
#pragma unroll
    for (int k = 0; k < 32; k += 8) {
        int r = bx + threadIdx.y + k, c = by + threadIdx.x;
        float v = t[threadIdx.x][threadIdx.y + k];
        __half h = __float2half(v);
        th[(size_t)r * DD + c] = h;
        tl[(size_t)r * DD + c] = __float2half(v - __half2float(h));
    }
}

// ---------------------------------------------------------------------------
// band softmax + fp16 P emit over padded window
// ---------------------------------------------------------------------------
__global__ void __launch_bounds__(128) band_softmax(
    float* __restrict__ att, __half* __restrict__ Ph)
{
    __shared__ float red[4];
    const int gid = blockIdx.x;
    const int b = gid >> 12;
    const int i = gid & (NN - 1);
    const size_t rowbase = ((size_t)b << 24) + ((size_t)i << 12);
    float* row = att + rowbase;
    int jlo = i - (AP - 1); if (jlo < 0) jlo = 0;
    int jhi = i + (AP - 1); if (jhi > NN - 1) jhi = NN - 1;
    const int cnt = jhi - jlo + 1;

    float v[4];
    int nc = 0;
    float m = -1e30f;
    for (int t = threadIdx.x; t < cnt; t += 128) { v[nc] = row[jlo + t]; m = fmaxf(m, v[nc]); nc++; }
    for (int o = 16; o > 0; o >>= 1) m = fmaxf(m, __shfl_xor_sync(0xffffffffu, m, o));
    const int w = threadIdx.x >> 5;
    if ((threadIdx.x & 31) == 0) red[w] = m;
    __syncthreads();
    m = fmaxf(fmaxf(red[0], red[1]), fmaxf(red[2], red[3]));
    __syncthreads();

    float s = 0.f;
    for (int c = 0; c < nc; c++) { v[c] = __expf(v[c] - m); s += v[c]; }
    for (int o = 16; o > 0; o >>= 1) s += __shfl_xor_sync(0xffffffffu, s, o);
    if ((threadIdx.x & 31) == 0) red[w] = s;
    __syncthreads();
    s = red[0] + red[1] + red[2] + red[3];
    const float inv = 1.0f / s;

    nc = 0;
    for (int t = threadIdx.x; t < cnt; t += 128) { row[jlo + t] = v[nc] * inv; nc++; }
    __syncthreads();

    int wlo = i - 256; wlo &= ~127; if (wlo < 0) wlo = 0;
    int whi = (i + 384) & ~127; if (whi > NN) whi = NN;
    for (int n = wlo + threadIdx.x; n < whi; n += 128) {
        float f = (n >= jlo && n <= jhi) ? row[n] : 0.f;
        Ph[rowbase + n] = __float2half(f);
    }
}

// ===========================================================================
// ptv: y[b,n,i] = sum_m P[b,m,n] * U[b,m,i]   (banded, 1-term, trans-ldsm)
// 4-stage single-barrier pipeline
// ===========================================================================
__device__ __forceinline__ void ptv_issue(
    uint32_t sbase, int tid,
    const __half* Phg, const __half* Uhg, int m0, int n0, int o0)
{
#pragma unroll
    for (int j = 0; j < 2; j++) {
        int e = tid + (j << 8);
        int r = e >> 4, c16 = e & 15;
        uint32_t sw = SW256((uint32_t)(r << 8) + (c16 << 4));
        cp16(sbase +         sw, Phg + (size_t)(m0 + r) * NN + n0 + (c16 << 3));
        cp16(sbase + 8192u + sw, Uhg + (size_t)(m0 + r) * DD + o0 + (c16 << 3));
    }
    asm volatile("cp.async.commit_group;" ::: "memory");
}

__device__ __forceinline__ void ptv_compute(
    float acc[4][4][4], uint32_t sb, int lane, int warp_m, int warp_n)
{
#pragma unroll
    for (int ks = 0; ks < 2; ks++) {
        const int m16 = ks << 4;
        uint32_t ah[4][4], bh[4][2];
        const int ar = m16 + ((lane >> 4) << 3) + (lane & 7);
        const int acsel = ((lane >> 3) & 1) << 3;
#pragma unroll
        for (int mi = 0; mi < 4; mi++) {
            int nb = warp_m*64 + mi*16 + acsel;
            ldsm4t(ah[mi], sb + SW256((uint32_t)(ar << 8) + (nb << 1)));
        }
        const int br = m16 + (((lane >> 3) & 1) << 3) + (lane & 7);
        const int bcsel = (lane >> 4) << 3;
#pragma unroll
        for (int jb = 0; jb < 2; jb++) {
            int ob = warp_n*32 + jb*16 + bcsel;
            uint32_t t4[4];
            ldsm4t(t4, sb + 8192u + SW256((uint32_t)(br << 8) + (ob << 1)));
            bh[jb*2][0] = t4[0]; bh[jb*2][1] = t4[1];
            bh[jb*2+1][0] = t4[2]; bh[jb*2+1][1] = t4[3];
        }
#pragma unroll
        for (int mi = 0; mi < 4; mi++)
#pragma unroll
            for (int ni = 0; ni < 4; ni++)
                mmah(acc[mi][ni], ah[mi], bh[ni]);
    }
}

__global__ void __launch_bounds__(256, 1) ptv_tc(
    const __half* __restrict__ Phg, const __half* __restrict__ Uhg,
    float* __restrict__ yout)
{
    const int bz = blockIdx.z;
    const int n0 = blockIdx.y << 7;
    const int o0 = blockIdx.x << 7;
    const __half* Pb = Phg + ((size_t)bz << 24);
    const __half* Ub = Uhg + ((size_t)bz << 22);

    extern __shared__ char smem[];
    uint32_t sb0 = smem_u32(smem);
    const int tid = threadIdx.x, lane = tid & 31, wid = tid >> 5;
    const int warp_m = wid >> 2, warp_n = wid & 3;

    int mlo = n0 - 256; if (mlo < 0) mlo = 0;
    int mhe = n0 + 384; if (mhe > NN) mhe = NN;
    const int NC = (mhe - mlo) >> 5;

    float acc[4][4][4] = {};

    ptv_issue(sb0,          tid, Pb, Ub, mlo,      n0, o0);
    ptv_issue(sb0 + 16384u, tid, Pb, Ub, mlo + 32, n0, o0);

    for (int i = 0; i < NC; i++) {
        if (i + 2 < NC) {
            ptv_issue(sb0 + ((i + 2) & 3)*16384u, tid,
                      Pb, Ub, mlo + ((i + 2) << 5), n0, o0);
            asm volatile("cp.async.wait_group 2;" ::: "memory");
        } else {
            asm volatile("cp.async.wait_group 0;" ::: "memory");
        }
        __syncthreads();
        ptv_compute(acc, sb0 + (i & 3)*16384u, lane, warp_m, warp_n);
    }

    float* yb = yout + ((size_t)bz << 22);
    const int rb = n0 + warp_m*64 + (lane >> 2);
    const int cb = o0 + warp_n*32 + (lane & 3)*2;
#pragma unroll
    for (int mi = 0; mi < 4; mi++)
#pragma unroll
        for (int ni = 0; ni < 4; ni++)
#pragma unroll
            for (int h = 0; h < 2; h++) {
                size_t off = (size_t)(rb + mi*16 + 8*h) * DD + cb + ni*8;
                *(float2*)&yb[off] = make_float2(acc[mi][ni][2*h + 0],
                                                 acc[mi][ni][2*h + 1]);
            }
}

// ---------------------------------------------------------------------------
extern "C" void kernel_launch(void* const* d_in, const int* in_sizes, int n_in,
                              void* d_out, int out_size)
{
    const float* x  = (const float*)d_in[0];
    const float* Wk = (const float*)d_in[1];
    const float* Wq = (const float*)d_in[2];
    const float* Wv = (const float*)d_in[3];
    const float* Wo = (const float*)d_in[4];

    float* y_out   = (float*)d_out;
    float* att_out = y_out + (size_t)BB * NN * DD;

    __half *xh, *xl, *WkTh, *WkTl, *WqTh, *WqTl, *WvTh, *WvTl, *Woh, *Wol;
    __half *Gh, *W2h, *Zh, *Uh, *Ph;
    cudaGetSymbolAddress((void**)&xh,   g_xh);   cudaGetSymbolAddress((void**)&xl,   g_xl);
    cudaGetSymbolAddress((void**)&WkTh, g_WkTh); cudaGetSymbolAddress((void**)&WkTl, g_WkTl);
    cudaGetSymbolAddress((void**)&WqTh, g_WqTh); cudaGetSymbolAddress((void**)&WqTl, g_WqTl);
    cudaGetSymbolAddress((void**)&WvTh, g_WvTh); cudaGetSymbolAddress((void**)&WvTl, g_WvTl);
    cudaGetSymbolAddress((void**)&Woh,  g_Woh);  cudaGetSymbolAddress((void**)&Wol,  g_Wol);
    cudaGetSymbolAddress((void**)&Gh,   g_Gh);   cudaGetSymbolAddress((void**)&W2h,  g_W2h);
    cudaGetSymbolAddress((void**)&Zh,   g_Zh);
    cudaGetSymbolAddress((void**)&Uh,   g_Uh);   cudaGetSymbolAddress((void**)&Ph,   g_Ph);

    cudaFuncSetAttribute((const void*)wgemm_tc, cudaFuncAttributeMaxDynamicSharedMemorySize, SM3);
    cudaFuncSetAttribute((const void*)zu_tc,    cudaFuncAttributeMaxDynamicSharedMemorySize, SM2);
    cudaFuncSetAttribute((const void*)band_tc,  cudaFuncAttributeMaxDynamicSharedMemorySize, SM1);
    cudaFuncSetAttribute((const void*)ptv_tc,   cudaFuncAttributeMaxDynamicSharedMemorySize, SM1);

    // 1. operand prep
    split2<<<4096, 256>>>(x, xh, xl, (BB * NN * DD) / 2);
    transpose_split3<<<dim3(32, 32, 3), dim3(32, 8)>>>(
        Wk, WkTh, WkTl, Wq, WqTh, WqTl, Wv, WvTh, WvTl);
    split2<<<512, 256>>>(Wo, Woh, Wol, (DD * DD) / 2);

    // 2. G = WkT @ WqT^T  and  W2 = Wo @ WvT^T  (one launch, 128 CTAs)
    wgemm_tc<<<dim3(8, 8, 2), 256, SM3>>>(WkTh, WkTl, WqTh, WqTl, Gh,
                                          Woh, Wol, WvTh, WvTl, W2h);

    // 3+4. Z = x @ G^T (2-term)  and  U = xh @ W2^T (1-term)  (one launch)
    zu_tc<<<dim3(8, 128, 2), 256, SM2>>>(xh, xl, Gh, W2h, Zh, Uh);

    // 5. banded logits = QS * Zh·xh^T (1-term; zeroes out-of-band att)
    band_tc<<<dim3(5, NN / 128, BB), 256, SM1>>>(Zh, xh, att_out);

    // 6. softmax + P emit
    band_softmax<<<BB * NN, 128>>>(att_out, Ph);

    // 7. y = P^T @ U (banded, 1-term, fp32 out — final)
    ptv_tc<<<dim3(DD / 128, NN / 128, BB), 256, SM1>>>(Ph, Uh, y_out);
}